// round 15
// baseline (speedup 1.0000x reference)
#include <cuda_runtime.h>
#include <cstdint>

#define MAXN 50048
#define MAXE 860000

// ---------------- scratch ----------------
__device__ float g_h[MAXN * 128];
__device__ float g_x2[MAXN * 128];
__device__ float g_as[MAXN];
__device__ float g_ad[MAXN];
__device__ int   g_deg[MAXN];
__device__ int   g_rank[MAXE];
__device__ int   g_rowptr[MAXN + 1];
__device__ int   g_esorted[MAXE];
__device__ int   g_aux[66];     // [0..63] partial sums, [64] done counter

// ---------------- tf32 helpers ----------------
__device__ __forceinline__ uint32_t f2tf32(float f) {
    uint32_t r;
    asm("cvt.rna.tf32.f32 %0, %1;" : "=r"(r) : "f"(f));
    return r;
}
__device__ __forceinline__ void mma_tf32(float& c0, float& c1, float& c2, float& c3,
                                         uint32_t a0, uint32_t a1, uint32_t a2, uint32_t a3,
                                         uint32_t b0, uint32_t b1) {
    asm("mma.sync.aligned.m16n8k8.row.col.f32.tf32.tf32.f32 "
        "{%0,%1,%2,%3}, {%4,%5,%6,%7}, {%8,%9}, {%0,%1,%2,%3};"
        : "+f"(c0), "+f"(c1), "+f"(c2), "+f"(c3)
        : "r"(a0), "r"(a1), "r"(a2), "r"(a3), "r"(b0), "r"(b1));
}

// ---------------- tf32 tensor-core GEMM (+alpha epilogue) ----------------
template <int BN>
__global__ void gemm_mma_alpha_kernel(const float* __restrict__ A, const float* __restrict__ B,
                                      float* __restrict__ C,
                                      const float* __restrict__ avs, const float* __restrict__ avd,
                                      int M, int K) {
    constexpr int NSUB = BN / 16;
    __shared__ uint32_t As[128][20];
    __shared__ uint32_t Bs[BN][20];
    __shared__ float shA[2][128];
    __shared__ float shD[2][128];

    const int tid = threadIdx.x;
    const int wid = tid >> 5;
    const int lane = tid & 31;
    const int g = lane >> 2;
    const int tg = lane & 3;
    const int wm = wid >> 1;
    const int wn = wid & 1;
    const int bm = blockIdx.x * 128;
    const int nbase = wn * (BN / 2);

    float acc[2][NSUB][4];
#pragma unroll
    for (int mi = 0; mi < 2; mi++)
#pragma unroll
        for (int ni = 0; ni < NSUB; ni++)
#pragma unroll
            for (int r = 0; r < 4; r++) acc[mi][ni][r] = 0.0f;

    for (int k0 = 0; k0 < K; k0 += 16) {
#pragma unroll
        for (int p = 0; p < 2; p++) {
            int fid = tid + p * 256;
            int row = fid >> 2;
            int ko = (fid & 3) * 4;
            float4 v = make_float4(0.f, 0.f, 0.f, 0.f);
            if (bm + row < M) v = *reinterpret_cast<const float4*>(&A[(size_t)(bm + row) * K + k0 + ko]);
            As[row][ko + 0] = f2tf32(v.x);
            As[row][ko + 1] = f2tf32(v.y);
            As[row][ko + 2] = f2tf32(v.z);
            As[row][ko + 3] = f2tf32(v.w);
        }
#pragma unroll
        for (int p = 0; p < BN / 64; p++) {
            int fid = tid + p * 256;
            int k = fid / (BN / 4);
            int nf = (fid % (BN / 4)) * 4;
            float4 v = *reinterpret_cast<const float4*>(&B[(size_t)(k0 + k) * BN + nf]);
            Bs[nf + 0][k] = f2tf32(v.x);
            Bs[nf + 1][k] = f2tf32(v.y);
            Bs[nf + 2][k] = f2tf32(v.z);
            Bs[nf + 3][k] = f2tf32(v.w);
        }
        __syncthreads();
#pragma unroll
        for (int ks = 0; ks < 2; ks++) {
            const int kb = ks * 8;
            uint32_t af[2][4];
#pragma unroll
            for (int mi = 0; mi < 2; mi++) {
                int row = wm * 32 + mi * 16 + g;
                af[mi][0] = As[row][kb + tg];
                af[mi][1] = As[row + 8][kb + tg];
                af[mi][2] = As[row][kb + tg + 4];
                af[mi][3] = As[row + 8][kb + tg + 4];
            }
#pragma unroll
            for (int ni = 0; ni < NSUB; ni++) {
                int nrow = nbase + ni * 8 + g;
                uint32_t b0 = Bs[nrow][kb + tg];
                uint32_t b1 = Bs[nrow][kb + tg + 4];
#pragma unroll
                for (int mi = 0; mi < 2; mi++)
                    mma_tf32(acc[mi][ni][0], acc[mi][ni][1], acc[mi][ni][2], acc[mi][ni][3],
                             af[mi][0], af[mi][1], af[mi][2], af[mi][3], b0, b1);
            }
        }
        __syncthreads();
    }

    float2 av2[NSUB], dv2[NSUB];
#pragma unroll
    for (int ni = 0; ni < NSUB; ni++) {
        int col = nbase + ni * 8 + tg * 2;
        av2[ni] = *reinterpret_cast<const float2*>(&avs[col]);
        dv2[ni] = *reinterpret_cast<const float2*>(&avd[col]);
    }

#pragma unroll
    for (int mi = 0; mi < 2; mi++) {
        float s0 = 0.f, d0 = 0.f, s1 = 0.f, d1 = 0.f;
        int row = bm + wm * 32 + mi * 16 + g;
#pragma unroll
        for (int ni = 0; ni < NSUB; ni++) {
            int col = nbase + ni * 8 + tg * 2;
            if (row < M)
                *reinterpret_cast<float2*>(&C[(size_t)row * BN + col]) =
                    make_float2(acc[mi][ni][0], acc[mi][ni][1]);
            if (row + 8 < M)
                *reinterpret_cast<float2*>(&C[(size_t)(row + 8) * BN + col]) =
                    make_float2(acc[mi][ni][2], acc[mi][ni][3]);
            s0 = fmaf(acc[mi][ni][0], av2[ni].x, fmaf(acc[mi][ni][1], av2[ni].y, s0));
            d0 = fmaf(acc[mi][ni][0], dv2[ni].x, fmaf(acc[mi][ni][1], dv2[ni].y, d0));
            s1 = fmaf(acc[mi][ni][2], av2[ni].x, fmaf(acc[mi][ni][3], av2[ni].y, s1));
            d1 = fmaf(acc[mi][ni][2], dv2[ni].x, fmaf(acc[mi][ni][3], dv2[ni].y, d1));
        }
#pragma unroll
        for (int o = 1; o <= 2; o <<= 1) {
            s0 += __shfl_xor_sync(0xffffffffu, s0, o);
            d0 += __shfl_xor_sync(0xffffffffu, d0, o);
            s1 += __shfl_xor_sync(0xffffffffu, s1, o);
            d1 += __shfl_xor_sync(0xffffffffu, d1, o);
        }
        if (tg == 0) {
            int lr = wm * 32 + mi * 16 + g;
            shA[wn][lr] = s0;
            shD[wn][lr] = d0;
            shA[wn][lr + 8] = s1;
            shD[wn][lr + 8] = d1;
        }
    }
    __syncthreads();
    if (tid < 128 && bm + tid < M) {
        g_as[bm + tid] = shA[0][tid] + shA[1][tid];
        g_ad[bm + tid] = shD[0][tid] + shD[1][tid];
    }
}

// ---------------- hist + rank, 8 edges per thread ----------------
__global__ void hist_kernel(const int* __restrict__ dst, int E, int ET) {
    int t = blockIdx.x * blockDim.x + threadIdx.x;
    int nv = E >> 3;
    if (t < nv) {
        int4 da = reinterpret_cast<const int4*>(dst)[2 * t];
        int4 db = reinterpret_cast<const int4*>(dst)[2 * t + 1];
        int4 ra, rb;
        ra.x = atomicAdd(&g_deg[da.x], 1);
        ra.y = atomicAdd(&g_deg[da.y], 1);
        ra.z = atomicAdd(&g_deg[da.z], 1);
        ra.w = atomicAdd(&g_deg[da.w], 1);
        rb.x = atomicAdd(&g_deg[db.x], 1);
        rb.y = atomicAdd(&g_deg[db.y], 1);
        rb.z = atomicAdd(&g_deg[db.z], 1);
        rb.w = atomicAdd(&g_deg[db.w], 1);
        reinterpret_cast<int4*>(&g_rank[t * 8])[0] = ra;
        reinterpret_cast<int4*>(&g_rank[t * 8])[1] = rb;
    } else {
        int i = (E & ~7) + (t - nv);
        if (i < ET) {
            int d = (i < E) ? __ldg(&dst[i]) : (i - E);
            g_rank[i] = atomicAdd(&g_deg[d], 1);
        }
    }
}

// ---------------- fused scan (decoupled lookback) + fill ----------------
// Grid must be a single resident wave (<=148 blocks of 1024 threads).
// Blocks [0, nb): block scan of g_deg -> g_rowptr, publish partial, bump done.
// All blocks: spin for done==nb, then fill g_esorted (8 edges/thread).
__global__ void scanfill_kernel(const int* __restrict__ src, const int* __restrict__ dst,
                                int E, int ET, int N, int nb) {
    __shared__ int wsum[32];
    __shared__ int lookval[64];
    __shared__ int sbase;
    const int t = threadIdx.x;
    const int lane = t & 31;
    const int wid = t >> 5;
    const int b = blockIdx.x;

    if (b < nb) {
        int i = b * 1024 + t;
        int v = (i < N) ? g_deg[i] : 0;
        int x = v;
#pragma unroll
        for (int o = 1; o < 32; o <<= 1) {
            int y = __shfl_up_sync(0xffffffffu, x, o);
            if (lane >= o) x += y;
        }
        if (lane == 31) wsum[wid] = x;
        __syncthreads();
        if (t < 32) {
            int w = wsum[t];
#pragma unroll
            for (int o = 1; o < 32; o <<= 1) {
                int y = __shfl_up_sync(0xffffffffu, w, o);
                if (t >= o) w += y;
            }
            wsum[t] = w;
        }
        __syncthreads();
        int incl = x + ((wid > 0) ? wsum[wid - 1] : 0);
        // publish this block's total (deg>=1 per node => total>0, so 0 == not ready)
        if (t == 0) atomicExch(&g_aux[b], wsum[31]);
        // parallel lookback
        if (t < b) {
            int pv;
            do { pv = atomicAdd(&g_aux[t], 0); } while (pv == 0);
            lookval[t] = pv;
        }
        __syncthreads();
        if (t == 0) {
            int s = 0;
            for (int j = 0; j < b; j++) s += lookval[j];
            sbase = s;
        }
        __syncthreads();
        int excl = sbase + incl - v;
        if (i < N) g_rowptr[i] = excl;
        if (i == N - 1) g_rowptr[N] = sbase + incl;
        __threadfence();
        __syncthreads();
        if (t == 0) atomicAdd(&g_aux[64], 1);
    }

    // ---- wait for rowptr complete ----
    if (t == 0) {
        while (atomicAdd(&g_aux[64], 0) < nb) { }
    }
    __syncthreads();
    __threadfence();

    // ---- fill phase: 8 edges per thread ----
    int gt = b * 1024 + t;
    int nv = E >> 3;
    if (gt < nv) {
        int4 sa = reinterpret_cast<const int4*>(src)[2 * gt];
        int4 sb = reinterpret_cast<const int4*>(src)[2 * gt + 1];
        int4 da = reinterpret_cast<const int4*>(dst)[2 * gt];
        int4 db = reinterpret_cast<const int4*>(dst)[2 * gt + 1];
        int4 ra = reinterpret_cast<const int4*>(&g_rank[gt * 8])[0];
        int4 rb = reinterpret_cast<const int4*>(&g_rank[gt * 8])[1];
        g_esorted[g_rowptr[da.x] + ra.x] = sa.x;
        g_esorted[g_rowptr[da.y] + ra.y] = sa.y;
        g_esorted[g_rowptr[da.z] + ra.z] = sa.z;
        g_esorted[g_rowptr[da.w] + ra.w] = sa.w;
        g_esorted[g_rowptr[db.x] + rb.x] = sb.x;
        g_esorted[g_rowptr[db.y] + rb.y] = sb.y;
        g_esorted[g_rowptr[db.z] + rb.z] = sb.z;
        g_esorted[g_rowptr[db.w] + rb.w] = sb.w;
    } else {
        int i = (E & ~7) + (gt - nv);
        if (i < ET) {
            int s, d;
            if (i < E) { s = __ldg(&src[i]); d = __ldg(&dst[i]); }
            else       { s = d = i - E; }
            g_esorted[g_rowptr[d] + g_rank[i]] = s;
        }
    }
}

// ---------------- gather: per-dst lane-group, fused softmax+agg+bias(+relu) ----------------
template <int F4, bool RELU>
__global__ void gather_kernel(const float* __restrict__ h,
                              const float* __restrict__ bias,
                              float* __restrict__ out, int N) {
    constexpr int NPW = 32 / F4;
    int warp = (blockIdx.x * blockDim.x + threadIdx.x) >> 5;
    int lane = threadIdx.x & 31;
    int sub = lane / F4;
    int li = lane % F4;
    int d = warp * NPW + sub;
    const unsigned gmask = ((F4 == 32) ? 0xffffffffu : ((1u << F4) - 1u) << (sub * F4));
    const int base = sub * F4;

    int start = 0, end = 0;
    float ad = 0.0f;
    if (d < N) {
        start = g_rowptr[d];
        end = g_rowptr[d + 1];
        ad = g_ad[d];
    }

    float4 acc = make_float4(0.f, 0.f, 0.f, 0.f);
    float den = 0.0f;
    const float4* h4 = reinterpret_cast<const float4*>(h);

    for (int e0 = start; e0 < end; e0 += F4) {
        int mye = e0 + li;
        float w = 0.0f;
        int s = 0;
        if (mye < end) {
            s = g_esorted[mye];
            float sc = g_as[s] + ad;
            sc = (sc >= 0.0f) ? sc : 0.2f * sc;
            w = __expf(sc);
        }
        den += w;
        int cnt = min(F4, end - e0);
        for (int j = 0; j < cnt; j++) {
            float wj = __shfl_sync(gmask, w, base + j);
            int sj = __shfl_sync(gmask, s, base + j);
            float4 hv = h4[(size_t)sj * F4 + li];
            acc.x = fmaf(wj, hv.x, acc.x);
            acc.y = fmaf(wj, hv.y, acc.y);
            acc.z = fmaf(wj, hv.z, acc.z);
            acc.w = fmaf(wj, hv.w, acc.w);
        }
    }
#pragma unroll
    for (int o = F4 / 2; o > 0; o >>= 1) den += __shfl_xor_sync(gmask, den, o);

    if (d < N) {
        float r = __frcp_rn(den);
        float4 b4 = reinterpret_cast<const float4*>(bias)[li];
        float4 v;
        v.x = fmaf(acc.x, r, b4.x);
        v.y = fmaf(acc.y, r, b4.y);
        v.z = fmaf(acc.z, r, b4.z);
        v.w = fmaf(acc.w, r, b4.w);
        if (RELU) {
            v.x = fmaxf(v.x, 0.f); v.y = fmaxf(v.y, 0.f);
            v.z = fmaxf(v.z, 0.f); v.w = fmaxf(v.w, 0.f);
        }
        reinterpret_cast<float4*>(out)[(size_t)d * F4 + li] = v;
    }
}

// ---------------- launch ----------------
extern "C" void kernel_launch(void* const* d_in, const int* in_sizes, int n_in,
                              void* d_out, int out_size) {
    const float* X     = (const float*)d_in[0];
    const int*   EI    = (const int*)d_in[1];
    const float* W1    = (const float*)d_in[2];
    const float* asrc1 = (const float*)d_in[3];
    const float* adst1 = (const float*)d_in[4];
    const float* b1    = (const float*)d_in[5];
    const float* W2    = (const float*)d_in[6];
    const float* asrc2 = (const float*)d_in[7];
    const float* adst2 = (const float*)d_in[8];
    const float* b2    = (const float*)d_in[9];
    float* out = (float*)d_out;

    const int F_IN = 128;
    const int N = in_sizes[0] / F_IN;
    const int E = in_sizes[1] / 2;
    const int ET = E + N;
    const int* src = EI;
    const int* dst = EI + E;

    float *p_h, *p_x2;
    int *p_deg, *p_aux;
    cudaGetSymbolAddress((void**)&p_h, g_h);
    cudaGetSymbolAddress((void**)&p_x2, g_x2);
    cudaGetSymbolAddress((void**)&p_deg, g_deg);
    cudaGetSymbolAddress((void**)&p_aux, g_aux);

    const int BT = 256;
    const int nb = (N + 1023) / 1024;                       // 49
    const int gB1 = (N + 127) / 128;
    const int e8T = (E >> 3) + (ET - (E & ~7));             // hist/fill threads
    const int sfB = ((e8T + 1023) / 1024) > nb ? ((e8T + 1023) / 1024) : nb;  // <=148

    static cudaStream_t s2 = nullptr;
    static cudaEvent_t evFork = nullptr, evJoin = nullptr;
    if (s2 == nullptr) {
        cudaStreamCreateWithFlags(&s2, cudaStreamNonBlocking);
        cudaEventCreateWithFlags(&evFork, cudaEventDisableTiming);
        cudaEventCreateWithFlags(&evJoin, cudaEventDisableTiming);
    }

    // ---- fork: CSR build on s2, GEMM1 on main stream ----
    cudaEventRecord(evFork, 0);
    cudaStreamWaitEvent(s2, evFork, 0);

    cudaMemsetAsync(p_deg, 0, (size_t)N * sizeof(int), s2);
    cudaMemsetAsync(p_aux, 0, 66 * sizeof(int), s2);
    hist_kernel<<<(e8T + BT - 1) / BT, BT, 0, s2>>>(dst, E, ET);
    scanfill_kernel<<<sfB, 1024, 0, s2>>>(src, dst, E, ET, N, nb);
    cudaEventRecord(evJoin, s2);

    // GEMM1 (+alpha1), tensor cores, concurrent with CSR build
    gemm_mma_alpha_kernel<128><<<gB1, BT>>>(X, W1, p_h, asrc1, adst1, N, F_IN);

    // ---- join ----
    cudaStreamWaitEvent(0, evJoin, 0);

    // gather layer 1 -> x2 (relu)
    gather_kernel<32, true><<<(N * 32 + BT - 1) / BT, BT>>>(p_h, b1, p_x2, N);

    // GEMM2 (+alpha2), tensor cores
    gemm_mma_alpha_kernel<64><<<gB1, BT>>>(p_x2, W2, p_h, asrc2, adst2, N, 128);

    // gather layer 2 -> out
    {
        long warps = (N + 1) / 2;
        gather_kernel<16, false><<<(unsigned)((warps * 32 + BT - 1) / BT), BT>>>(p_h, b2, out, N);
    }
}

// round 16
// speedup vs baseline: 1.0102x; 1.0102x over previous
#include <cuda_runtime.h>
#include <cstdint>

#define MAXN 50048
#define MAXE 860000

// ---------------- scratch ----------------
__device__ float g_h[MAXN * 128];
__device__ float g_x2[MAXN * 128];
__device__ float g_as[MAXN];
__device__ float g_ad[MAXN];
__device__ int   g_deg[MAXN];
__device__ int   g_rank[MAXE];
__device__ int   g_rowptr[MAXN + 1];
__device__ int   g_esorted[MAXE];
__device__ int   g_blocksum[64];

// ---------------- tf32 helpers ----------------
__device__ __forceinline__ uint32_t f2tf32(float f) {
    uint32_t r;
    asm("cvt.rna.tf32.f32 %0, %1;" : "=r"(r) : "f"(f));
    return r;
}
__device__ __forceinline__ void mma_tf32(float& c0, float& c1, float& c2, float& c3,
                                         uint32_t a0, uint32_t a1, uint32_t a2, uint32_t a3,
                                         uint32_t b0, uint32_t b1) {
    asm("mma.sync.aligned.m16n8k8.row.col.f32.tf32.tf32.f32 "
        "{%0,%1,%2,%3}, {%4,%5,%6,%7}, {%8,%9}, {%0,%1,%2,%3};"
        : "+f"(c0), "+f"(c1), "+f"(c2), "+f"(c3)
        : "r"(a0), "r"(a1), "r"(a2), "r"(a3), "r"(b0), "r"(b1));
}

// ---------------- tf32 tensor-core GEMM (+alpha epilogue) ----------------
template <int BN>
__global__ void gemm_mma_alpha_kernel(const float* __restrict__ A, const float* __restrict__ B,
                                      float* __restrict__ C,
                                      const float* __restrict__ avs, const float* __restrict__ avd,
                                      int M, int K) {
    constexpr int NSUB = BN / 16;
    __shared__ uint32_t As[128][20];
    __shared__ uint32_t Bs[BN][20];
    __shared__ float shA[2][128];
    __shared__ float shD[2][128];

    const int tid = threadIdx.x;
    const int wid = tid >> 5;
    const int lane = tid & 31;
    const int g = lane >> 2;
    const int tg = lane & 3;
    const int wm = wid >> 1;
    const int wn = wid & 1;
    const int bm = blockIdx.x * 128;
    const int nbase = wn * (BN / 2);

    float acc[2][NSUB][4];
#pragma unroll
    for (int mi = 0; mi < 2; mi++)
#pragma unroll
        for (int ni = 0; ni < NSUB; ni++)
#pragma unroll
            for (int r = 0; r < 4; r++) acc[mi][ni][r] = 0.0f;

    for (int k0 = 0; k0 < K; k0 += 16) {
#pragma unroll
        for (int p = 0; p < 2; p++) {
            int fid = tid + p * 256;
            int row = fid >> 2;
            int ko = (fid & 3) * 4;
            float4 v = make_float4(0.f, 0.f, 0.f, 0.f);
            if (bm + row < M) v = *reinterpret_cast<const float4*>(&A[(size_t)(bm + row) * K + k0 + ko]);
            As[row][ko + 0] = f2tf32(v.x);
            As[row][ko + 1] = f2tf32(v.y);
            As[row][ko + 2] = f2tf32(v.z);
            As[row][ko + 3] = f2tf32(v.w);
        }
#pragma unroll
        for (int p = 0; p < BN / 64; p++) {
            int fid = tid + p * 256;
            int k = fid / (BN / 4);
            int nf = (fid % (BN / 4)) * 4;
            float4 v = *reinterpret_cast<const float4*>(&B[(size_t)(k0 + k) * BN + nf]);
            Bs[nf + 0][k] = f2tf32(v.x);
            Bs[nf + 1][k] = f2tf32(v.y);
            Bs[nf + 2][k] = f2tf32(v.z);
            Bs[nf + 3][k] = f2tf32(v.w);
        }
        __syncthreads();
#pragma unroll
        for (int ks = 0; ks < 2; ks++) {
            const int kb = ks * 8;
            uint32_t af[2][4];
#pragma unroll
            for (int mi = 0; mi < 2; mi++) {
                int row = wm * 32 + mi * 16 + g;
                af[mi][0] = As[row][kb + tg];
                af[mi][1] = As[row + 8][kb + tg];
                af[mi][2] = As[row][kb + tg + 4];
                af[mi][3] = As[row + 8][kb + tg + 4];
            }
#pragma unroll
            for (int ni = 0; ni < NSUB; ni++) {
                int nrow = nbase + ni * 8 + g;
                uint32_t b0 = Bs[nrow][kb + tg];
                uint32_t b1 = Bs[nrow][kb + tg + 4];
#pragma unroll
                for (int mi = 0; mi < 2; mi++)
                    mma_tf32(acc[mi][ni][0], acc[mi][ni][1], acc[mi][ni][2], acc[mi][ni][3],
                             af[mi][0], af[mi][1], af[mi][2], af[mi][3], b0, b1);
            }
        }
        __syncthreads();
    }

    float2 av2[NSUB], dv2[NSUB];
#pragma unroll
    for (int ni = 0; ni < NSUB; ni++) {
        int col = nbase + ni * 8 + tg * 2;
        av2[ni] = *reinterpret_cast<const float2*>(&avs[col]);
        dv2[ni] = *reinterpret_cast<const float2*>(&avd[col]);
    }

#pragma unroll
    for (int mi = 0; mi < 2; mi++) {
        float s0 = 0.f, d0 = 0.f, s1 = 0.f, d1 = 0.f;
        int row = bm + wm * 32 + mi * 16 + g;
#pragma unroll
        for (int ni = 0; ni < NSUB; ni++) {
            int col = nbase + ni * 8 + tg * 2;
            if (row < M)
                *reinterpret_cast<float2*>(&C[(size_t)row * BN + col]) =
                    make_float2(acc[mi][ni][0], acc[mi][ni][1]);
            if (row + 8 < M)
                *reinterpret_cast<float2*>(&C[(size_t)(row + 8) * BN + col]) =
                    make_float2(acc[mi][ni][2], acc[mi][ni][3]);
            s0 = fmaf(acc[mi][ni][0], av2[ni].x, fmaf(acc[mi][ni][1], av2[ni].y, s0));
            d0 = fmaf(acc[mi][ni][0], dv2[ni].x, fmaf(acc[mi][ni][1], dv2[ni].y, d0));
            s1 = fmaf(acc[mi][ni][2], av2[ni].x, fmaf(acc[mi][ni][3], av2[ni].y, s1));
            d1 = fmaf(acc[mi][ni][2], dv2[ni].x, fmaf(acc[mi][ni][3], dv2[ni].y, d1));
        }
#pragma unroll
        for (int o = 1; o <= 2; o <<= 1) {
            s0 += __shfl_xor_sync(0xffffffffu, s0, o);
            d0 += __shfl_xor_sync(0xffffffffu, d0, o);
            s1 += __shfl_xor_sync(0xffffffffu, s1, o);
            d1 += __shfl_xor_sync(0xffffffffu, d1, o);
        }
        if (tg == 0) {
            int lr = wm * 32 + mi * 16 + g;
            shA[wn][lr] = s0;
            shD[wn][lr] = d0;
            shA[wn][lr + 8] = s1;
            shD[wn][lr + 8] = d1;
        }
    }
    __syncthreads();
    if (tid < 128 && bm + tid < M) {
        g_as[bm + tid] = shA[0][tid] + shA[1][tid];
        g_ad[bm + tid] = shD[0][tid] + shD[1][tid];
    }
}

// ---------------- hist + rank, 8 edges per thread ----------------
__global__ void hist_kernel(const int* __restrict__ dst, int E, int ET) {
    int t = blockIdx.x * blockDim.x + threadIdx.x;
    int nv = E >> 3;
    if (t < nv) {
        int4 da = reinterpret_cast<const int4*>(dst)[2 * t];
        int4 db = reinterpret_cast<const int4*>(dst)[2 * t + 1];
        int4 ra, rb;
        ra.x = atomicAdd(&g_deg[da.x], 1);
        ra.y = atomicAdd(&g_deg[da.y], 1);
        ra.z = atomicAdd(&g_deg[da.z], 1);
        ra.w = atomicAdd(&g_deg[da.w], 1);
        rb.x = atomicAdd(&g_deg[db.x], 1);
        rb.y = atomicAdd(&g_deg[db.y], 1);
        rb.z = atomicAdd(&g_deg[db.z], 1);
        rb.w = atomicAdd(&g_deg[db.w], 1);
        reinterpret_cast<int4*>(&g_rank[t * 8])[0] = ra;
        reinterpret_cast<int4*>(&g_rank[t * 8])[1] = rb;
    } else {
        int i = (E & ~7) + (t - nv);
        if (i < ET) {
            int d = (i < E) ? __ldg(&dst[i]) : (i - E);
            g_rank[i] = atomicAdd(&g_deg[d], 1);
        }
    }
}

// ---------------- scans ----------------
__global__ void scan_partial_kernel(int N) {
    __shared__ int wsum[32];
    int t = threadIdx.x;
    int i = blockIdx.x * 1024 + t;
    int v = (i < N) ? g_deg[i] : 0;
#pragma unroll
    for (int o = 16; o > 0; o >>= 1) v += __shfl_xor_sync(0xffffffffu, v, o);
    if ((t & 31) == 0) wsum[t >> 5] = v;
    __syncthreads();
    if (t < 32) {
        int x = wsum[t];
#pragma unroll
        for (int o = 16; o > 0; o >>= 1) x += __shfl_xor_sync(0xffffffffu, x, o);
        if (t == 0) g_blocksum[blockIdx.x] = x;
    }
}

__global__ void scan_final_kernel(int N, int nb) {
    __shared__ int wsum[32];
    __shared__ int bsm[64];
    __shared__ int base_sh;
    int t = threadIdx.x;
    int lane = t & 31;
    int wid = t >> 5;
    int i = blockIdx.x * 1024 + t;
    int v = (i < N) ? g_deg[i] : 0;
    int x = v;
#pragma unroll
    for (int o = 1; o < 32; o <<= 1) {
        int y = __shfl_up_sync(0xffffffffu, x, o);
        if (lane >= o) x += y;
    }
    if (lane == 31) wsum[wid] = x;
    if (t < nb) bsm[t] = g_blocksum[t];
    __syncthreads();
    if (t < 32) {
        int w = wsum[t];
#pragma unroll
        for (int o = 1; o < 32; o <<= 1) {
            int y = __shfl_up_sync(0xffffffffu, w, o);
            if (t >= o) w += y;
        }
        wsum[t] = w;
    }
    if (t == 0) {
        int s = 0;
        for (int j = 0; j < blockIdx.x; j++) s += bsm[j];
        base_sh = s;
        if (blockIdx.x == 0) {
            int tot = 0;
            for (int j = 0; j < nb; j++) tot += bsm[j];
            g_rowptr[N] = tot;
        }
    }
    __syncthreads();
    int incl = x + ((wid > 0) ? wsum[wid - 1] : 0);
    int excl = base_sh + incl - v;
    if (i < N) g_rowptr[i] = excl;
}

// ---------------- fill: no atomics, 4 edges per thread ----------------
__global__ void fill_kernel(const int* __restrict__ src, const int* __restrict__ dst,
                            int E, int ET) {
    int t = blockIdx.x * blockDim.x + threadIdx.x;
    int nv = E >> 2;
    if (t < nv) {
        int4 s4 = reinterpret_cast<const int4*>(src)[t];
        int4 d4 = reinterpret_cast<const int4*>(dst)[t];
        int4 r4 = *reinterpret_cast<const int4*>(&g_rank[t * 4]);
        g_esorted[g_rowptr[d4.x] + r4.x] = s4.x;
        g_esorted[g_rowptr[d4.y] + r4.y] = s4.y;
        g_esorted[g_rowptr[d4.z] + r4.z] = s4.z;
        g_esorted[g_rowptr[d4.w] + r4.w] = s4.w;
    } else {
        int i = (E & ~3) + (t - nv);
        if (i < ET) {
            int s, d;
            if (i < E) { s = __ldg(&src[i]); d = __ldg(&dst[i]); }
            else       { s = d = i - E; }
            g_esorted[g_rowptr[d] + g_rank[i]] = s;
        }
    }
}

// ---------------- gather: per-dst lane-group, fused softmax+agg+bias(+relu) ----------------
// __launch_bounds__(256, 8) forces <=32 regs -> 100% theoretical occupancy.
template <int F4, bool RELU>
__global__ void __launch_bounds__(256, 8)
gather_kernel(const float* __restrict__ h,
              const float* __restrict__ bias,
              float* __restrict__ out, int N) {
    constexpr int NPW = 32 / F4;
    int warp = (blockIdx.x * blockDim.x + threadIdx.x) >> 5;
    int lane = threadIdx.x & 31;
    int sub = lane / F4;
    int li = lane % F4;
    int d = warp * NPW + sub;
    const unsigned gmask = ((F4 == 32) ? 0xffffffffu : ((1u << F4) - 1u) << (sub * F4));
    const int base = sub * F4;

    int start = 0, end = 0;
    float ad = 0.0f;
    if (d < N) {
        start = g_rowptr[d];
        end = g_rowptr[d + 1];
        ad = g_ad[d];
    }

    float4 acc = make_float4(0.f, 0.f, 0.f, 0.f);
    float den = 0.0f;
    const float4* h4 = reinterpret_cast<const float4*>(h);

    for (int e0 = start; e0 < end; e0 += F4) {
        int mye = e0 + li;
        float w = 0.0f;
        int s = 0;
        if (mye < end) {
            s = g_esorted[mye];
            float sc = g_as[s] + ad;
            sc = (sc >= 0.0f) ? sc : 0.2f * sc;
            w = __expf(sc);
        }
        den += w;
        int cnt = min(F4, end - e0);
        for (int j = 0; j < cnt; j++) {
            float wj = __shfl_sync(gmask, w, base + j);
            int sj = __shfl_sync(gmask, s, base + j);
            float4 hv = h4[(size_t)sj * F4 + li];
            acc.x = fmaf(wj, hv.x, acc.x);
            acc.y = fmaf(wj, hv.y, acc.y);
            acc.z = fmaf(wj, hv.z, acc.z);
            acc.w = fmaf(wj, hv.w, acc.w);
        }
    }
#pragma unroll
    for (int o = F4 / 2; o > 0; o >>= 1) den += __shfl_xor_sync(gmask, den, o);

    if (d < N) {
        float r = __frcp_rn(den);
        float4 b4 = reinterpret_cast<const float4*>(bias)[li];
        float4 v;
        v.x = fmaf(acc.x, r, b4.x);
        v.y = fmaf(acc.y, r, b4.y);
        v.z = fmaf(acc.z, r, b4.z);
        v.w = fmaf(acc.w, r, b4.w);
        if (RELU) {
            v.x = fmaxf(v.x, 0.f); v.y = fmaxf(v.y, 0.f);
            v.z = fmaxf(v.z, 0.f); v.w = fmaxf(v.w, 0.f);
        }
        reinterpret_cast<float4*>(out)[(size_t)d * F4 + li] = v;
    }
}

// ---------------- launch ----------------
extern "C" void kernel_launch(void* const* d_in, const int* in_sizes, int n_in,
                              void* d_out, int out_size) {
    const float* X     = (const float*)d_in[0];
    const int*   EI    = (const int*)d_in[1];
    const float* W1    = (const float*)d_in[2];
    const float* asrc1 = (const float*)d_in[3];
    const float* adst1 = (const float*)d_in[4];
    const float* b1    = (const float*)d_in[5];
    const float* W2    = (const float*)d_in[6];
    const float* asrc2 = (const float*)d_in[7];
    const float* adst2 = (const float*)d_in[8];
    const float* b2    = (const float*)d_in[9];
    float* out = (float*)d_out;

    const int F_IN = 128;
    const int N = in_sizes[0] / F_IN;
    const int E = in_sizes[1] / 2;
    const int ET = E + N;
    const int* src = EI;
    const int* dst = EI + E;

    float *p_h, *p_x2;
    int *p_deg;
    cudaGetSymbolAddress((void**)&p_h, g_h);
    cudaGetSymbolAddress((void**)&p_x2, g_x2);
    cudaGetSymbolAddress((void**)&p_deg, g_deg);

    const int BT = 256;
    const int nb = (N + 1023) / 1024;
    const int gB1 = (N + 127) / 128;
    const int e8T = (E >> 3) + (ET - (E & ~7));
    const int e4T = (E >> 2) + (ET - (E & ~3));

    static cudaStream_t s2 = nullptr;
    static cudaEvent_t evFork = nullptr, evJoin = nullptr;
    if (s2 == nullptr) {
        cudaStreamCreateWithFlags(&s2, cudaStreamNonBlocking);
        cudaEventCreateWithFlags(&evFork, cudaEventDisableTiming);
        cudaEventCreateWithFlags(&evJoin, cudaEventDisableTiming);
    }

    // ---- fork: CSR build on s2, GEMM1 on main stream ----
    cudaEventRecord(evFork, 0);
    cudaStreamWaitEvent(s2, evFork, 0);

    cudaMemsetAsync(p_deg, 0, (size_t)N * sizeof(int), s2);
    hist_kernel<<<(e8T + BT - 1) / BT, BT, 0, s2>>>(dst, E, ET);
    scan_partial_kernel<<<nb, 1024, 0, s2>>>(N);
    scan_final_kernel<<<nb, 1024, 0, s2>>>(N, nb);
    fill_kernel<<<(e4T + BT - 1) / BT, BT, 0, s2>>>(src, dst, E, ET);
    cudaEventRecord(evJoin, s2);

    // GEMM1 (+alpha1), tensor cores, concurrent with CSR build
    gemm_mma_alpha_kernel<128><<<gB1, BT>>>(X, W1, p_h, asrc1, adst1, N, F_IN);

    // ---- join ----
    cudaStreamWaitEvent(0, evJoin, 0);

    // gather layer 1 -> x2 (relu)
    gather_kernel<32, true><<<(N * 32 + BT - 1) / BT, BT>>>(p_h, b1, p_x2, N);

    // GEMM2 (+alpha2), tensor cores
    gemm_mma_alpha_kernel<64><<<gB1, BT>>>(p_x2, W2, p_h, asrc2, adst2, N, 128);

    // gather layer 2 -> out
    {
        long warps = (N + 1) / 2;
        gather_kernel<16, false><<<(unsigned)((warps * 32 + BT - 1) / BT), BT>>>(p_h, b2, out, N);
    }
}